// round 11
// baseline (speedup 1.0000x reference)
#include <cuda_runtime.h>

#define BB 8
#define NN 2048
#define NH 8
#define MAT 16384
#define SCALE (1.0f/16384.0f)   // 1/(N*NH)
#define SA  132                 // A smem row stride (floats)
#define SBN 136                 // B smem row stride (floats)
#define SZB ((64 * SA + 128 * SBN) * 4)   // 103424 B — uniform for ALL launches
#define NT  256                 // threads per block (8 warps)

// ---------------- scratch (device globals) ----------------
__device__ __align__(16) float g_part[16 * BB * MAT];
__device__ __align__(16) float g_G[2][BB * MAT];
__device__ __align__(16) float g_R [BB * MAT];
__device__ __align__(16) float g_Wp[BB * NH * MAT];
__device__ __align__(16) float g_Wq[BB * MAT];
__device__ __align__(16) float g_U [BB * MAT];

// ---------------- PDL intrinsics ----------------
__device__ __forceinline__ void gdep_wait() {
    asm volatile("griddepcontrol.wait;" ::: "memory");
}
__device__ __forceinline__ void gdep_go() {
    asm volatile("griddepcontrol.launch_dependents;");
}

// ---------------- tf32 helpers ----------------
__device__ __forceinline__ float tf(float x) {
    float y; asm("cvt.rna.tf32.f32 %0, %1;" : "=f"(y) : "f"(x)); return y;
}
__device__ __forceinline__ float4 tf4(float4 x) {
    x.x = tf(x.x); x.y = tf(x.y); x.z = tf(x.z); x.w = tf(x.w); return x;
}
__device__ __forceinline__ void mma8(float c[4], const float a[4], const float b[2]) {
    asm volatile(
        "mma.sync.aligned.m16n8k8.row.col.f32.tf32.tf32.f32 "
        "{%0,%1,%2,%3}, {%4,%5,%6,%7}, {%8,%9}, {%0,%1,%2,%3};"
        : "+f"(c[0]), "+f"(c[1]), "+f"(c[2]), "+f"(c[3])
        : "r"(__float_as_uint(a[0])), "r"(__float_as_uint(a[1])),
          "r"(__float_as_uint(a[2])), "r"(__float_as_uint(a[3])),
          "r"(__float_as_uint(b[0])), "r"(__float_as_uint(b[1])));
}

// ---------------- smem fills (256 threads) ----------------
__device__ __forceinline__ void fillA64(const float* __restrict__ A, int lda,
                                        float* __restrict__ As) {
#pragma unroll
    for (int i = 0; i < 8; i++) {
        int idx = threadIdx.x + NT * i;
        int m = idx >> 5, kf = (idx & 31) * 4;
        *(float4*)(As + m * SA + kf) = tf4(*(const float4*)(A + m * lda + kf));
    }
}
__device__ __forceinline__ void fillAT64(const float* __restrict__ A, int lda,
                                         int moff, float* __restrict__ As) {
#pragma unroll
    for (int i = 0; i < 8; i++) {
        int idx = threadIdx.x + NT * i;
        int k = idx >> 4, mf = (idx & 15) * 4;
        float4 x = tf4(*(const float4*)(A + k * lda + moff + mf));
        As[(mf + 0) * SA + k] = x.x;
        As[(mf + 1) * SA + k] = x.y;
        As[(mf + 2) * SA + k] = x.z;
        As[(mf + 3) * SA + k] = x.w;
    }
}
__device__ __forceinline__ void fillB(const float* __restrict__ B, int ldb,
                                      float* __restrict__ Bs) {
#pragma unroll
    for (int i = 0; i < 16; i++) {
        int idx = threadIdx.x + NT * i;
        int k = idx >> 5, nf = (idx & 31) * 4;
        *(float4*)(Bs + k * SBN + nf) = tf4(*(const float4*)(B + k * ldb + nf));
    }
}
__device__ __forceinline__ void fillB2(const float* __restrict__ B1,
                                       const float* __restrict__ B2,
                                       float* __restrict__ Bs) {
#pragma unroll
    for (int i = 0; i < 16; i++) {
        int idx = threadIdx.x + NT * i;
        int k = idx >> 5, nf = (idx & 31) * 4;
        float4 x = *(const float4*)(B1 + k * 128 + nf);
        float4 y = *(const float4*)(B2 + k * 128 + nf);
        x.x += y.x; x.y += y.y; x.z += y.z; x.w += y.w;
        *(float4*)(Bs + k * SBN + nf) = tf4(x);
    }
}
__device__ __forceinline__ void fillBT(const float* __restrict__ B, int ldb,
                                       float* __restrict__ Bs) {
#pragma unroll
    for (int i = 0; i < 16; i++) {
        int idx = threadIdx.x + NT * i;
        int n = idx >> 5, kf = (idx & 31) * 4;
        float4 x = tf4(*(const float4*)(B + n * ldb + kf));
        Bs[(kf + 0) * SBN + n] = x.x;
        Bs[(kf + 1) * SBN + n] = x.y;
        Bs[(kf + 2) * SBN + n] = x.z;
        Bs[(kf + 3) * SBN + n] = x.w;
    }
}

// ---------------- compute core: 64x128 tile, K=128, 8 warps of 32x32 ------
__device__ __forceinline__ void compute64(const float* __restrict__ As,
                                          const float* __restrict__ Bs,
                                          float acc[2][4][4]) {
    const int lane = threadIdx.x & 31, warp = threadIdx.x >> 5;
    const int mr = (warp & 1) * 32, nc = (warp >> 1) * 32;
    const int ar = lane >> 2, ac = lane & 3;
    const int bk = lane & 3,  bn = lane >> 2;
#pragma unroll
    for (int kk = 0; kk < 128; kk += 8) {
        float a[2][4];
#pragma unroll
        for (int i = 0; i < 2; i++) {
            const float* p = As + (mr + 16 * i + ar) * SA + kk + ac;
            a[i][0] = p[0]; a[i][1] = p[8 * SA]; a[i][2] = p[4]; a[i][3] = p[8 * SA + 4];
        }
#pragma unroll
        for (int j = 0; j < 4; j++) {
            const float* qp = Bs + (kk + bk) * SBN + nc + 8 * j + bn;
            float b[2] = { qp[0], qp[4 * SBN] };
            mma8(acc[0][j], a[0], b);
            mma8(acc[1][j], a[1], b);
        }
    }
}
__device__ __forceinline__ void zacc(float a[2][4][4]) {
#pragma unroll
    for (int i = 0; i < 2; i++)
#pragma unroll
        for (int j = 0; j < 4; j++)
#pragma unroll
            for (int r = 0; r < 4; r++) a[i][j][r] = 0.0f;
}

// ---------------- epilogue / T-store ----------------
__device__ __forceinline__ void epi64(float* __restrict__ C,
                                      const float* __restrict__ a1,
                                      const float* __restrict__ a2,
                                      float acc[2][4][4]) {
    const int lane = threadIdx.x & 31, warp = threadIdx.x >> 5;
    const int r0 = (warp & 1) * 32 + (lane >> 2);
    const int c0 = (warp >> 1) * 32 + 2 * (lane & 3);
#pragma unroll
    for (int i = 0; i < 2; i++)
#pragma unroll
        for (int j = 0; j < 4; j++) {
            int r = r0 + 16 * i, c = c0 + 8 * j;
            float2 lo = make_float2(acc[i][j][0], acc[i][j][1]);
            float2 hi = make_float2(acc[i][j][2], acc[i][j][3]);
            if (a1) {
                float2 x = *(const float2*)(a1 + r * 128 + c);
                float2 y = *(const float2*)(a1 + (r + 8) * 128 + c);
                lo.x += x.x; lo.y += x.y; hi.x += y.x; hi.y += y.y;
            }
            if (a2) {
                float2 x = *(const float2*)(a2 + r * 128 + c);
                float2 y = *(const float2*)(a2 + (r + 8) * 128 + c);
                lo.x += x.x; lo.y += x.y; hi.x += y.x; hi.y += y.y;
            }
            *(float2*)(C + r * 128 + c)       = lo;
            *(float2*)(C + (r + 8) * 128 + c) = hi;
        }
}
__device__ __forceinline__ void storeT64(float* __restrict__ As,
                                         float acc[2][4][4]) {
    const int lane = threadIdx.x & 31, warp = threadIdx.x >> 5;
    const int r0 = (warp & 1) * 32 + (lane >> 2);
    const int c0 = (warp >> 1) * 32 + 2 * (lane & 3);
#pragma unroll
    for (int i = 0; i < 2; i++)
#pragma unroll
        for (int j = 0; j < 4; j++) {
            int r = r0 + 16 * i, c = c0 + 8 * j;
            As[r * SA + c]           = tf(acc[i][j][0]);
            As[r * SA + c + 1]       = tf(acc[i][j][1]);
            As[(r + 8) * SA + c]     = tf(acc[i][j][2]);
            As[(r + 8) * SA + c + 1] = tf(acc[i][j][3]);
        }
}

// ---------------- kernels ----------------

// part[chunk,b] slab = (Zc^T)_slab @ Zc      grid (16, 8, 2)
__global__ __launch_bounds__(NT) void k_g0(const float* __restrict__ Z,
                                           float* __restrict__ part) {
    extern __shared__ float sm[];
    float* As = sm; float* Bs = sm + 64 * SA;
    gdep_wait(); gdep_go();                      // no upstream deps
    int chunk = blockIdx.x, b = blockIdx.y, mh = blockIdx.z;
    const float* Zc = Z + (b * NN + chunk * 128) * 128;
    fillAT64(Zc, 128, mh * 64, As);
    fillB(Zc, 128, Bs);
    __syncthreads();
    float acc[2][4][4]; zacc(acc);
    compute64(As, Bs, acc);
    epi64(part + (chunk * BB + b) * MAT + mh * 64 * 128, 0, 0, acc);
}

// G[0] = sum over 16 chunks (float4)          grid (128)
__global__ __launch_bounds__(NT) void k_reduce(const float* __restrict__ part,
                                               float* __restrict__ G) {
    gdep_wait(); gdep_go();
    int e = (blockIdx.x * NT + threadIdx.x) * 4;   // 131072 floats
    int b = e >> 14, i = e & 16383;
    float4 s = make_float4(0.f, 0.f, 0.f, 0.f);
#pragma unroll
    for (int c = 0; c < 16; c++) {
        float4 x = *(const float4*)(part + (c * BB + b) * MAT + i);
        s.x += x.x; s.y += x.y; s.z += x.z; s.w += x.w;
    }
    *(float4*)(G + e) = s;
}

// fused T = Q@G, W = T@V^T                     grid (8, 8, 2)
__global__ __launch_bounds__(NT) void k_TW(const float* __restrict__ q,
                                           const float* __restrict__ v,
                                           const float* __restrict__ G,
                                           float* __restrict__ Wp, int l) {
    extern __shared__ float sm[];
    float* As = sm; float* Bs = sm + 64 * SA;
    int j = blockIdx.x, b = blockIdx.y, mh = blockIdx.z;
    fillA64(q + (l * NH + j) * MAT + mh * 64 * 128, 128, As);  // input: pre-wait OK
    gdep_wait(); gdep_go();
    fillB(G + b * MAT, 128, Bs);                 // G from predecessor chain
    __syncthreads();
    float acc[2][4][4]; zacc(acc);
    compute64(As, Bs, acc);
    __syncthreads();
    storeT64(As, acc);
    fillBT(v + (l * NH + j) * MAT, 128, Bs);
    __syncthreads();
    zacc(acc);
    compute64(As, Bs, acc);
    epi64(Wp + (b * NH + j) * MAT + mh * 64 * 128, 0, 0, acc);
}

// W'[b] = SCALE * sum_j Wp[b,j]; layer 0 also R = W'   grid (128)
__global__ __launch_bounds__(NT) void k_Wsum(const float* __restrict__ Wp,
                                             float* __restrict__ Wq,
                                             float* __restrict__ R, int copyR) {
    gdep_wait(); gdep_go();
    int e = (blockIdx.x * NT + threadIdx.x) * 4;
    int b = e >> 14, i = e & 16383;
    float4 s = make_float4(0.f, 0.f, 0.f, 0.f);
#pragma unroll
    for (int j = 0; j < NH; j++) {
        float4 x = *(const float4*)(Wp + (b * NH + j) * MAT + i);
        s.x += x.x; s.y += x.y; s.z += x.z; s.w += x.w;
    }
    s.x *= SCALE; s.y *= SCALE; s.z *= SCALE; s.w *= SCALE;
    *(float4*)(Wq + e) = s;
    if (copyR) *(float4*)(R + e) = s;
}

// C1: z=0: U slab = G slab @ W' ; z=1: R slab = R + W' + R@W'   grid (2,8,zz)
__global__ __launch_bounds__(NT) void k_C1(const float* __restrict__ G,
                                           float* __restrict__ R,
                                           const float* __restrict__ Wq,
                                           float* __restrict__ U) {
    extern __shared__ float sm[];
    float* As = sm; float* Bs = sm + 64 * SA;
    int mh = blockIdx.x, b = blockIdx.y, which = blockIdx.z;
    const float* Ap = (which ? R : G) + b * MAT + mh * 64 * 128;
    fillA64(Ap, 128, As);                        // G/R: >=3 kernels old, pre-wait OK
    gdep_wait(); gdep_go();
    fillB(Wq + b * MAT, 128, Bs);                // Wq from immediate predecessor
    __syncthreads();
    float acc[2][4][4]; zacc(acc);
    compute64(As, Bs, acc);
    if (which) epi64(R + b * MAT + mh * 64 * 128,
                     R  + b * MAT + mh * 64 * 128,
                     Wq + b * MAT + mh * 64 * 128, acc);
    else       epi64(U + b * MAT + mh * 64 * 128, 0, 0, acc);
}

// C2: Gnext slab = W'^T slab @ (G+U) + G + U      grid (2, 8)
__global__ __launch_bounds__(NT) void k_C2(const float* __restrict__ Wq,
                                           const float* __restrict__ G,
                                           const float* __restrict__ U,
                                           float* __restrict__ Gn) {
    extern __shared__ float sm[];
    float* As = sm; float* Bs = sm + 64 * SA;
    int mh = blockIdx.x, b = blockIdx.y;
    fillAT64(Wq + b * MAT, 128, mh * 64, As);    // Wq: 2 kernels back, pre-wait OK
    gdep_wait(); gdep_go();
    fillB2(G + b * MAT, U + b * MAT, Bs);        // U from immediate predecessor
    __syncthreads();
    float acc[2][4][4]; zacc(acc);
    compute64(As, Bs, acc);
    epi64(Gn + b * MAT + mh * 64 * 128,
          G  + b * MAT + mh * 64 * 128,
          U  + b * MAT + mh * 64 * 128, acc);
}

// out tile: Y = Zt + Zt@R2 (exact, pre-wait), out = Y + Y@W'3   grid (32, 8)
__global__ __launch_bounds__(NT) void k_out(const float* __restrict__ Z,
                                            const float* __restrict__ R,
                                            const float* __restrict__ Wq,
                                            float* __restrict__ out) {
    extern __shared__ float sm[];
    float* As = sm; float* Bs = sm + 64 * SA;
    int tile = blockIdx.x, b = blockIdx.y;
    const float* Zt = Z + (b * NN + tile * 64) * 128;
    // GEMM1 uses only Z (input) and R (written at layer 2, >=3 kernels back)
    fillA64(Zt, 128, As);
    fillB(R + b * MAT, 128, Bs);
    __syncthreads();
    float acc[2][4][4]; zacc(acc);
    compute64(As, Bs, acc);

    const int lane = threadIdx.x & 31, warp = threadIdx.x >> 5;
    const int r0 = (warp & 1) * 32 + (lane >> 2);
    const int c0 = (warp >> 1) * 32 + 2 * (lane & 3);
    float Y[2][4][4];
#pragma unroll
    for (int i = 0; i < 2; i++)
#pragma unroll
        for (int j = 0; j < 4; j++) {
            int r = r0 + 16 * i, c = c0 + 8 * j;
            Y[i][j][0] = acc[i][j][0] + Zt[r * 128 + c];
            Y[i][j][1] = acc[i][j][1] + Zt[r * 128 + c + 1];
            Y[i][j][2] = acc[i][j][2] + Zt[(r + 8) * 128 + c];
            Y[i][j][3] = acc[i][j][3] + Zt[(r + 8) * 128 + c + 1];
        }
    __syncthreads();
    storeT64(As, Y);                 // As <- tf(Y)
    gdep_wait(); gdep_go();          // now need W'_3 from Wsum
    fillB(Wq + b * MAT, 128, Bs);
    __syncthreads();
    float acc2[2][4][4]; zacc(acc2);
    compute64(As, Bs, acc2);

    float* Ct = out + (b * NN + tile * 64) * 128;
#pragma unroll
    for (int i = 0; i < 2; i++)
#pragma unroll
        for (int j = 0; j < 4; j++) {
            int r = r0 + 16 * i, c = c0 + 8 * j;
            *(float2*)(Ct + r * 128 + c) =
                make_float2(Y[i][j][0] + acc2[i][j][0], Y[i][j][1] + acc2[i][j][1]);
            *(float2*)(Ct + (r + 8) * 128 + c) =
                make_float2(Y[i][j][2] + acc2[i][j][2], Y[i][j][3] + acc2[i][j][3]);
        }
}

// ---------------- host ----------------
extern "C" void kernel_launch(void* const* d_in, const int* in_sizes, int n_in,
                              void* d_out, int out_size) {
    const float* Z = (const float*)d_in[0];
    const float* v = (const float*)d_in[1];
    const float* q = (const float*)d_in[2];
    float* out = (float*)d_out;

    cudaFuncSetAttribute(k_g0,     cudaFuncAttributeMaxDynamicSharedMemorySize, SZB);
    cudaFuncSetAttribute(k_reduce, cudaFuncAttributeMaxDynamicSharedMemorySize, SZB);
    cudaFuncSetAttribute(k_TW,     cudaFuncAttributeMaxDynamicSharedMemorySize, SZB);
    cudaFuncSetAttribute(k_Wsum,   cudaFuncAttributeMaxDynamicSharedMemorySize, SZB);
    cudaFuncSetAttribute(k_C1,     cudaFuncAttributeMaxDynamicSharedMemorySize, SZB);
    cudaFuncSetAttribute(k_C2,     cudaFuncAttributeMaxDynamicSharedMemorySize, SZB);
    cudaFuncSetAttribute(k_out,    cudaFuncAttributeMaxDynamicSharedMemorySize, SZB);

    float *pPart, *pG, *pR, *pWp, *pWq, *pU;
    cudaGetSymbolAddress((void**)&pPart, g_part);
    cudaGetSymbolAddress((void**)&pG,  g_G);
    cudaGetSymbolAddress((void**)&pR,  g_R);
    cudaGetSymbolAddress((void**)&pWp, g_Wp);
    cudaGetSymbolAddress((void**)&pWq, g_Wq);
    cudaGetSymbolAddress((void**)&pU,  g_U);

    float* Gbuf[2] = { pG, pG + BB * MAT };

    cudaLaunchAttribute attr[1];
    attr[0].id = cudaLaunchAttributeProgrammaticStreamSerialization;
    attr[0].val.programmaticStreamSerializationAllowed = 1;

    cudaLaunchConfig_t cfg = {};
    cfg.blockDim = dim3(NT, 1, 1);
    cfg.dynamicSmemBytes = SZB;
    cfg.stream = 0;
    cfg.attrs = attr;
    cfg.numAttrs = 1;

    cfg.gridDim = dim3(16, BB, 2);
    cudaLaunchKernelEx(&cfg, k_g0, Z, pPart);
    cfg.gridDim = dim3(128, 1, 1);
    cudaLaunchKernelEx(&cfg, k_reduce, (const float*)pPart, Gbuf[0]);

    int cur = 0;
    for (int l = 0; l < 4; l++) {
        cfg.gridDim = dim3(NH, BB, 2);
        cudaLaunchKernelEx(&cfg, k_TW, q, v, (const float*)Gbuf[cur], pWp, l);
        cfg.gridDim = dim3(128, 1, 1);
        cudaLaunchKernelEx(&cfg, k_Wsum, (const float*)pWp, pWq, pR, l == 0 ? 1 : 0);
        if (l < 3) {
            cfg.gridDim = dim3(2, BB, (l == 0) ? 1 : 2);
            cudaLaunchKernelEx(&cfg, k_C1, (const float*)Gbuf[cur], pR,
                               (const float*)pWq, pU);
            cfg.gridDim = dim3(2, BB, 1);
            cudaLaunchKernelEx(&cfg, k_C2, (const float*)pWq,
                               (const float*)Gbuf[cur], (const float*)pU,
                               Gbuf[cur ^ 1]);
            cur ^= 1;
        }
    }

    cfg.gridDim = dim3(32, BB, 1);
    cudaLaunchKernelEx(&cfg, k_out, Z, (const float*)pR, (const float*)pWq, out);
}

// round 12
// speedup vs baseline: 1.1339x; 1.1339x over previous
#include <cuda_runtime.h>

#define BB 8
#define NN 2048
#define NH 8
#define MAT 16384
#define SCALE (1.0f/16384.0f)   // 1/(N*NH)
#define SA  132                 // A smem row stride (floats)
#define SBN 136                 // B smem row stride (floats)
#define SZB ((64 * SA + 128 * SBN) * 4)   // 103424 B for GEMM kernels
#define NT  256                 // threads per block (8 warps)

// ---------------- scratch (device globals) ----------------
__device__ __align__(16) float g_part[16 * BB * MAT];
__device__ __align__(16) float g_G[2][BB * MAT];
__device__ __align__(16) float g_R [BB * MAT];
__device__ __align__(16) float g_Wp[BB * NH * MAT];
__device__ __align__(16) float g_Wq[BB * MAT];

// ---------------- tf32 helpers ----------------
__device__ __forceinline__ float tf(float x) {
    float y; asm("cvt.rna.tf32.f32 %0, %1;" : "=f"(y) : "f"(x)); return y;
}
__device__ __forceinline__ float4 tf4(float4 x) {
    x.x = tf(x.x); x.y = tf(x.y); x.z = tf(x.z); x.w = tf(x.w); return x;
}
__device__ __forceinline__ void mma8(float c[4], const float a[4], const float b[2]) {
    asm volatile(
        "mma.sync.aligned.m16n8k8.row.col.f32.tf32.tf32.f32 "
        "{%0,%1,%2,%3}, {%4,%5,%6,%7}, {%8,%9}, {%0,%1,%2,%3};"
        : "+f"(c[0]), "+f"(c[1]), "+f"(c[2]), "+f"(c[3])
        : "r"(__float_as_uint(a[0])), "r"(__float_as_uint(a[1])),
          "r"(__float_as_uint(a[2])), "r"(__float_as_uint(a[3])),
          "r"(__float_as_uint(b[0])), "r"(__float_as_uint(b[1])));
}

// ---------------- smem fills (256 threads) ----------------
__device__ __forceinline__ void fillA64(const float* __restrict__ A, int lda,
                                        float* __restrict__ As) {
#pragma unroll
    for (int i = 0; i < 8; i++) {
        int idx = threadIdx.x + NT * i;
        int m = idx >> 5, kf = (idx & 31) * 4;
        *(float4*)(As + m * SA + kf) = tf4(*(const float4*)(A + m * lda + kf));
    }
}
__device__ __forceinline__ void fillAT64(const float* __restrict__ A, int lda,
                                         int moff, float* __restrict__ As) {
#pragma unroll
    for (int i = 0; i < 8; i++) {
        int idx = threadIdx.x + NT * i;
        int k = idx >> 4, mf = (idx & 15) * 4;
        float4 x = tf4(*(const float4*)(A + k * lda + moff + mf));
        As[(mf + 0) * SA + k] = x.x;
        As[(mf + 1) * SA + k] = x.y;
        As[(mf + 2) * SA + k] = x.z;
        As[(mf + 3) * SA + k] = x.w;
    }
}
__device__ __forceinline__ void fillB(const float* __restrict__ B, int ldb,
                                      float* __restrict__ Bs) {
#pragma unroll
    for (int i = 0; i < 16; i++) {
        int idx = threadIdx.x + NT * i;
        int k = idx >> 5, nf = (idx & 31) * 4;
        *(float4*)(Bs + k * SBN + nf) = tf4(*(const float4*)(B + k * ldb + nf));
    }
}
// Bs[k][n] = tf(B[k*128+n] + (k==n))   -> M = I + W'
__device__ __forceinline__ void fillB_plusI(const float* __restrict__ B,
                                            float* __restrict__ Bs) {
#pragma unroll
    for (int i = 0; i < 16; i++) {
        int idx = threadIdx.x + NT * i;
        int k = idx >> 5, nf = (idx & 31) * 4;
        float4 x = *(const float4*)(B + k * 128 + nf);
        if (k == nf)     x.x += 1.0f;
        if (k == nf + 1) x.y += 1.0f;
        if (k == nf + 2) x.z += 1.0f;
        if (k == nf + 3) x.w += 1.0f;
        *(float4*)(Bs + k * SBN + nf) = tf4(x);
    }
}
__device__ __forceinline__ void fillBT(const float* __restrict__ B, int ldb,
                                       float* __restrict__ Bs) {
#pragma unroll
    for (int i = 0; i < 16; i++) {
        int idx = threadIdx.x + NT * i;
        int n = idx >> 5, kf = (idx & 31) * 4;
        float4 x = tf4(*(const float4*)(B + n * ldb + kf));
        Bs[(kf + 0) * SBN + n] = x.x;
        Bs[(kf + 1) * SBN + n] = x.y;
        Bs[(kf + 2) * SBN + n] = x.z;
        Bs[(kf + 3) * SBN + n] = x.w;
    }
}

// ---------------- compute core: 64x128 tile, K=128, 8 warps of 32x32 ------
__device__ __forceinline__ void compute64(const float* __restrict__ As,
                                          const float* __restrict__ Bs,
                                          float acc[2][4][4]) {
    const int lane = threadIdx.x & 31, warp = threadIdx.x >> 5;
    const int mr = (warp & 1) * 32, nc = (warp >> 1) * 32;
    const int ar = lane >> 2, ac = lane & 3;
    const int bk = lane & 3,  bn = lane >> 2;
#pragma unroll
    for (int kk = 0; kk < 128; kk += 8) {
        float a[2][4];
#pragma unroll
        for (int i = 0; i < 2; i++) {
            const float* p = As + (mr + 16 * i + ar) * SA + kk + ac;
            a[i][0] = p[0]; a[i][1] = p[8 * SA]; a[i][2] = p[4]; a[i][3] = p[8 * SA + 4];
        }
#pragma unroll
        for (int j = 0; j < 4; j++) {
            const float* qp = Bs + (kk + bk) * SBN + nc + 8 * j + bn;
            float b[2] = { qp[0], qp[4 * SBN] };
            mma8(acc[0][j], a[0], b);
            mma8(acc[1][j], a[1], b);
        }
    }
}
__device__ __forceinline__ void zacc(float a[2][4][4]) {
#pragma unroll
    for (int i = 0; i < 2; i++)
#pragma unroll
        for (int j = 0; j < 4; j++)
#pragma unroll
            for (int r = 0; r < 4; r++) a[i][j][r] = 0.0f;
}

// ---------------- epilogue / T-store ----------------
__device__ __forceinline__ void epi64(float* __restrict__ C,
                                      const float* __restrict__ a1,
                                      const float* __restrict__ a2,
                                      float acc[2][4][4]) {
    const int lane = threadIdx.x & 31, warp = threadIdx.x >> 5;
    const int r0 = (warp & 1) * 32 + (lane >> 2);
    const int c0 = (warp >> 1) * 32 + 2 * (lane & 3);
#pragma unroll
    for (int i = 0; i < 2; i++)
#pragma unroll
        for (int j = 0; j < 4; j++) {
            int r = r0 + 16 * i, c = c0 + 8 * j;
            float2 lo = make_float2(acc[i][j][0], acc[i][j][1]);
            float2 hi = make_float2(acc[i][j][2], acc[i][j][3]);
            if (a1) {
                float2 x = *(const float2*)(a1 + r * 128 + c);
                float2 y = *(const float2*)(a1 + (r + 8) * 128 + c);
                lo.x += x.x; lo.y += x.y; hi.x += y.x; hi.y += y.y;
            }
            if (a2) {
                float2 x = *(const float2*)(a2 + r * 128 + c);
                float2 y = *(const float2*)(a2 + (r + 8) * 128 + c);
                lo.x += x.x; lo.y += x.y; hi.x += y.x; hi.y += y.y;
            }
            *(float2*)(C + r * 128 + c)       = lo;
            *(float2*)(C + (r + 8) * 128 + c) = hi;
        }
}
// As <- tf(acc)  (64x128, A layout)
__device__ __forceinline__ void storeT64(float* __restrict__ As,
                                         float acc[2][4][4]) {
    const int lane = threadIdx.x & 31, warp = threadIdx.x >> 5;
    const int r0 = (warp & 1) * 32 + (lane >> 2);
    const int c0 = (warp >> 1) * 32 + 2 * (lane & 3);
#pragma unroll
    for (int i = 0; i < 2; i++)
#pragma unroll
        for (int j = 0; j < 4; j++) {
            int r = r0 + 16 * i, c = c0 + 8 * j;
            As[r * SA + c]           = tf(acc[i][j][0]);
            As[r * SA + c + 1]       = tf(acc[i][j][1]);
            As[(r + 8) * SA + c]     = tf(acc[i][j][2]);
            As[(r + 8) * SA + c + 1] = tf(acc[i][j][3]);
        }
}
// As <- tf(acc + add[r*128+c])   (X = W'^T_slab G + G_slab)
__device__ __forceinline__ void storeT64_add(float* __restrict__ As,
                                             float acc[2][4][4],
                                             const float* __restrict__ add) {
    const int lane = threadIdx.x & 31, warp = threadIdx.x >> 5;
    const int r0 = (warp & 1) * 32 + (lane >> 2);
    const int c0 = (warp >> 1) * 32 + 2 * (lane & 3);
#pragma unroll
    for (int i = 0; i < 2; i++)
#pragma unroll
        for (int j = 0; j < 4; j++) {
            int r = r0 + 16 * i, c = c0 + 8 * j;
            float2 x = *(const float2*)(add + r * 128 + c);
            float2 y = *(const float2*)(add + (r + 8) * 128 + c);
            As[r * SA + c]           = tf(acc[i][j][0] + x.x);
            As[r * SA + c + 1]       = tf(acc[i][j][1] + x.y);
            As[(r + 8) * SA + c]     = tf(acc[i][j][2] + y.x);
            As[(r + 8) * SA + c + 1] = tf(acc[i][j][3] + y.y);
        }
}

// ---------------- kernels ----------------

// part[chunk,b] slab = (Zc^T)_slab @ Zc      grid (16, 8, 2)
__global__ __launch_bounds__(NT) void k_g0(const float* __restrict__ Z,
                                           float* __restrict__ part) {
    extern __shared__ float sm[];
    float* As = sm; float* Bs = sm + 64 * SA;
    int chunk = blockIdx.x, b = blockIdx.y, mh = blockIdx.z;
    const float* Zc = Z + (b * NN + chunk * 128) * 128;
    fillAT64(Zc, 128, mh * 64, As);
    fillB(Zc, 128, Bs);
    __syncthreads();
    float acc[2][4][4]; zacc(acc);
    compute64(As, Bs, acc);
    epi64(part + (chunk * BB + b) * MAT + mh * 64 * 128, 0, 0, acc);
}

// G[0] = sum over 16 chunks (float4)          grid (256) x 128 thr
__global__ __launch_bounds__(128) void k_reduce(const float* __restrict__ part,
                                                float* __restrict__ G) {
    int e = (blockIdx.x * 128 + threadIdx.x) * 4;   // 131072 floats
    int b = e >> 14, i = e & 16383;
    float4 s = make_float4(0.f, 0.f, 0.f, 0.f);
#pragma unroll
    for (int c = 0; c < 16; c++) {
        float4 x = *(const float4*)(part + (c * BB + b) * MAT + i);
        s.x += x.x; s.y += x.y; s.z += x.z; s.w += x.w;
    }
    *(float4*)(G + e) = s;
}

// fused T = Q@G, W = T@V^T                     grid (8, 8, 2)
__global__ __launch_bounds__(NT) void k_TW(const float* __restrict__ q,
                                           const float* __restrict__ v,
                                           const float* __restrict__ G,
                                           float* __restrict__ Wp, int l) {
    extern __shared__ float sm[];
    float* As = sm; float* Bs = sm + 64 * SA;
    int j = blockIdx.x, b = blockIdx.y, mh = blockIdx.z;
    fillA64(q + (l * NH + j) * MAT + mh * 64 * 128, 128, As);
    fillB(G + b * MAT, 128, Bs);
    __syncthreads();
    float acc[2][4][4]; zacc(acc);
    compute64(As, Bs, acc);
    __syncthreads();
    storeT64(As, acc);
    fillBT(v + (l * NH + j) * MAT, 128, Bs);
    __syncthreads();
    zacc(acc);
    compute64(As, Bs, acc);
    epi64(Wp + (b * NH + j) * MAT + mh * 64 * 128, 0, 0, acc);
}

// W'[b] = SCALE * sum_j Wp[b,j]; layer 0 also R = W'   grid (256) x 128 thr
__global__ __launch_bounds__(128) void k_Wsum(const float* __restrict__ Wp,
                                              float* __restrict__ Wq,
                                              float* __restrict__ R, int copyR) {
    int e = (blockIdx.x * 128 + threadIdx.x) * 4;
    int b = e >> 14, i = e & 16383;
    float4 s = make_float4(0.f, 0.f, 0.f, 0.f);
#pragma unroll
    for (int j = 0; j < NH; j++) {
        float4 x = *(const float4*)(Wp + (b * NH + j) * MAT + i);
        s.x += x.x; s.y += x.y; s.z += x.z; s.w += x.w;
    }
    s.x *= SCALE; s.y *= SCALE; s.z *= SCALE; s.w *= SCALE;
    *(float4*)(Wq + e) = s;
    if (copyR) *(float4*)(R + e) = s;
}

// C: z=0: Gnext slab = (M^T)_slab G M  (two chained GEMMs, M = I + W')
//    z=1: R slab = R + W' + R@W'
// grid (2, 8, zz)
__global__ __launch_bounds__(NT) void k_C(const float* __restrict__ Wq,
                                          const float* __restrict__ G,
                                          float* __restrict__ R,
                                          float* __restrict__ Gn) {
    extern __shared__ float sm[];
    float* As = sm; float* Bs = sm + 64 * SA;
    int mh = blockIdx.x, b = blockIdx.y, which = blockIdx.z;
    if (which == 0) {
        // GEMM1: acc = (W'^T)_slab @ G ; X = acc + G_slab (tf32 into As)
        fillAT64(Wq + b * MAT, 128, mh * 64, As);
        fillB(G + b * MAT, 128, Bs);
        __syncthreads();
        float acc[2][4][4]; zacc(acc);
        compute64(As, Bs, acc);
        __syncthreads();
        storeT64_add(As, acc, G + b * MAT + mh * 64 * 128);
        fillB_plusI(Wq + b * MAT, Bs);        // M = I + W'
        __syncthreads();
        float acc2[2][4][4]; zacc(acc2);
        compute64(As, Bs, acc2);
        epi64(Gn + b * MAT + mh * 64 * 128, 0, 0, acc2);
    } else {
        float* Rp = R + b * MAT + mh * 64 * 128;
        fillA64(Rp, 128, As);
        fillB(Wq + b * MAT, 128, Bs);
        __syncthreads();
        float acc[2][4][4]; zacc(acc);
        compute64(As, Bs, acc);
        epi64(Rp, Rp, Wq + b * MAT + mh * 64 * 128, acc);
    }
}

// out tile: Y = Zt + Zt@R2 (exact in regs), out = Y + Y@W'3   grid (32, 8)
__global__ __launch_bounds__(NT) void k_out(const float* __restrict__ Z,
                                            const float* __restrict__ R,
                                            const float* __restrict__ Wq,
                                            float* __restrict__ out) {
    extern __shared__ float sm[];
    float* As = sm; float* Bs = sm + 64 * SA;
    int tile = blockIdx.x, b = blockIdx.y;
    const float* Zt = Z + (b * NN + tile * 64) * 128;
    fillA64(Zt, 128, As);
    fillB(R + b * MAT, 128, Bs);
    __syncthreads();
    float acc[2][4][4]; zacc(acc);
    compute64(As, Bs, acc);

    const int lane = threadIdx.x & 31, warp = threadIdx.x >> 5;
    const int r0 = (warp & 1) * 32 + (lane >> 2);
    const int c0 = (warp >> 1) * 32 + 2 * (lane & 3);
    float Y[2][4][4];
#pragma unroll
    for (int i = 0; i < 2; i++)
#pragma unroll
        for (int j = 0; j < 4; j++) {
            int r = r0 + 16 * i, c = c0 + 8 * j;
            Y[i][j][0] = acc[i][j][0] + Zt[r * 128 + c];
            Y[i][j][1] = acc[i][j][1] + Zt[r * 128 + c + 1];
            Y[i][j][2] = acc[i][j][2] + Zt[(r + 8) * 128 + c];
            Y[i][j][3] = acc[i][j][3] + Zt[(r + 8) * 128 + c + 1];
        }
    __syncthreads();
    storeT64(As, Y);                 // As <- tf(Y)
    fillB(Wq + b * MAT, 128, Bs);    // Bs <- W'_3
    __syncthreads();
    float acc2[2][4][4]; zacc(acc2);
    compute64(As, Bs, acc2);

    float* Ct = out + (b * NN + tile * 64) * 128;
#pragma unroll
    for (int i = 0; i < 2; i++)
#pragma unroll
        for (int j = 0; j < 4; j++) {
            int r = r0 + 16 * i, c = c0 + 8 * j;
            *(float2*)(Ct + r * 128 + c) =
                make_float2(Y[i][j][0] + acc2[i][j][0], Y[i][j][1] + acc2[i][j][1]);
            *(float2*)(Ct + (r + 8) * 128 + c) =
                make_float2(Y[i][j][2] + acc2[i][j][2], Y[i][j][3] + acc2[i][j][3]);
        }
}

// ---------------- host ----------------
extern "C" void kernel_launch(void* const* d_in, const int* in_sizes, int n_in,
                              void* d_out, int out_size) {
    const float* Z = (const float*)d_in[0];
    const float* v = (const float*)d_in[1];
    const float* q = (const float*)d_in[2];
    float* out = (float*)d_out;

    cudaFuncSetAttribute(k_g0,  cudaFuncAttributeMaxDynamicSharedMemorySize, SZB);
    cudaFuncSetAttribute(k_TW,  cudaFuncAttributeMaxDynamicSharedMemorySize, SZB);
    cudaFuncSetAttribute(k_C,   cudaFuncAttributeMaxDynamicSharedMemorySize, SZB);
    cudaFuncSetAttribute(k_out, cudaFuncAttributeMaxDynamicSharedMemorySize, SZB);

    float *pPart, *pG, *pR, *pWp, *pWq;
    cudaGetSymbolAddress((void**)&pPart, g_part);
    cudaGetSymbolAddress((void**)&pG,  g_G);
    cudaGetSymbolAddress((void**)&pR,  g_R);
    cudaGetSymbolAddress((void**)&pWp, g_Wp);
    cudaGetSymbolAddress((void**)&pWq, g_Wq);

    float* Gbuf[2] = { pG, pG + BB * MAT };

    k_g0    <<<dim3(16, BB, 2), NT, SZB>>>(Z, pPart);
    k_reduce<<<256, 128>>>(pPart, Gbuf[0]);

    int cur = 0;
    for (int l = 0; l < 4; l++) {
        k_TW  <<<dim3(NH, BB, 2), NT, SZB>>>(q, v, Gbuf[cur], pWp, l);
        k_Wsum<<<256, 128>>>(pWp, pWq, pR, l == 0 ? 1 : 0);
        if (l < 3) {
            int zz = (l == 0) ? 1 : 2;
            k_C<<<dim3(2, BB, zz), NT, SZB>>>(pWq, Gbuf[cur], pR, Gbuf[cur ^ 1]);
            cur ^= 1;
        }
    }

    k_out<<<dim3(32, BB), NT, SZB>>>(Z, pR, pWq, out);
}